// round 16
// baseline (speedup 1.0000x reference)
#include <cuda_runtime.h>
#include <cuda_bf16.h>
#include <math.h>

#define Bq 16
#define NN 8192
#define WD 128
#define MD 32
#define NL 4
#define PCHA 40        // A smem pitch (bf16): 16B-aligned rows, conflict-free ldmatrix
#define PCHB 136       // B smem pitch

typedef __nv_bfloat16 bf;

// ---- static device scratch ----
__device__ __align__(16) bf g_hh0[Bq*NN*WD];
__device__ __align__(16) bf g_hl0[Bq*NN*WD];
__device__ __align__(16) bf g_hh1[Bq*NN*WD];
__device__ __align__(16) bf g_hl1[Bq*NN*WD];
__device__ __align__(16) bf g_FblkH[64*NN];   // [n-chunk32][64 r][32]
__device__ __align__(16) bf g_FblkL[64*NN];
__device__ __align__(16) bf g_FnmH[NN*64];    // [n][r]
__device__ __align__(16) bf g_FnmL[NN*64];
__device__ __align__(16) bf g_skwH[NL*WD*WD]; // [l][k][o]
__device__ __align__(16) bf g_skwL[NL*WD*WD];
__device__ __align__(16) bf g_w1H[WD*WD];     // [k][o]
__device__ __align__(16) bf g_w1L[WD*WD];
__device__ __align__(16) bf g_YbH[Bq*64*WD];  // [b][j][o]: j<32 Yr', j>=32 -Yi'
__device__ __align__(16) bf g_YbL[Bq*64*WD];
__device__ float g_Xp[Bq*64*64*WD];           // split-K partials, 64 chunks
__device__ float g_X0[Bq*64];                 // layer-0 x-DFT
__device__ float g_wrT[NL*MD*WD*WD];
__device__ float g_wiT[NL*MD*WD*WD];

__device__ __forceinline__ void f2bb(float x, bf &h, bf &l){
  h = __float2bfloat16(x);
  l = __float2bfloat16(x - __bfloat162float(h));
}
__device__ __forceinline__ float gelu_f(float v){
  return 0.5f*v*(1.0f + erff(v*0.70710678118654752f));
}
__device__ __forceinline__ void mma16816(float* d, const unsigned* a, const unsigned* b){
  asm volatile("mma.sync.aligned.m16n8k16.row.col.f32.bf16.bf16.f32 "
    "{%0,%1,%2,%3},{%4,%5,%6,%7},{%8,%9},{%0,%1,%2,%3};\n"
    : "+f"(d[0]),"+f"(d[1]),"+f"(d[2]),"+f"(d[3])
    : "r"(a[0]),"r"(a[1]),"r"(a[2]),"r"(a[3]),"r"(b[0]),"r"(b[1]));
}
__device__ __forceinline__ void ldsm4(unsigned* d, unsigned addr){
  asm volatile("ldmatrix.sync.aligned.m8n8.x4.shared.b16 {%0,%1,%2,%3}, [%4];"
    : "=r"(d[0]),"=r"(d[1]),"=r"(d[2]),"=r"(d[3]) : "r"(addr));
}
__device__ __forceinline__ void ldsm4t(unsigned* d, unsigned addr){
  asm volatile("ldmatrix.sync.aligned.m8n8.x4.trans.shared.b16 {%0,%1,%2,%3}, [%4];"
    : "=r"(d[0]),"=r"(d[1]),"=r"(d[2]),"=r"(d[3]) : "r"(addr));
}
__device__ __forceinline__ void cpa16(unsigned dst, const void* src){
  asm volatile("cp.async.cg.shared.global [%0], [%1], 16;" :: "r"(dst), "l"(src));
}
#define CP_COMMIT asm volatile("cp.async.commit_group;")
#define CP_WAIT   asm volatile("cp.async.wait_group 0;")

// 3-pass hi/lo mma over K=32: warp tile 64x32 (A pitch PCHA)
__device__ __forceinline__ void mma_stage(unsigned aH, unsigned aL,
    unsigned bH, unsigned bL, float (&acc)[4][4][4]){
  #pragma unroll
  for (int ks=0; ks<2; ks++){
    unsigned kA = ks*32;
    unsigned kB = ks*16*(PCHB*2);
    unsigned af[4][4], bh[8], bl[8];
    ldsm4t(&bh[0], bH + kB);
    ldsm4t(&bh[4], bH + kB + 32);
    #pragma unroll
    for (int mi=0;mi<4;mi++) ldsm4(af[mi], aH + mi*(16*PCHA*2) + kA);
    #pragma unroll
    for (int mi=0;mi<4;mi++)
      #pragma unroll
      for (int ni=0;ni<4;ni++) mma16816(acc[mi][ni], af[mi], &bh[ni*2]);
    ldsm4t(&bl[0], bL + kB);
    ldsm4t(&bl[4], bL + kB + 32);
    #pragma unroll
    for (int mi=0;mi<4;mi++)
      #pragma unroll
      for (int ni=0;ni<4;ni++) mma16816(acc[mi][ni], af[mi], &bl[ni*2]);
    #pragma unroll
    for (int mi=0;mi<4;mi++) ldsm4(af[mi], aL + mi*(16*PCHA*2) + kA);
    #pragma unroll
    for (int mi=0;mi<4;mi++)
      #pragma unroll
      for (int ni=0;ni<4;ni++) mma16816(acc[mi][ni], af[mi], &bh[ni*2]);
  }
}
// same but A pitch PCHB (A = stashed h tile) — fused head GEMM
__device__ __forceinline__ void mma_stageHD(unsigned aH, unsigned aL,
    unsigned bH, unsigned bL, float (&acc)[4][4][4]){
  #pragma unroll
  for (int ks=0; ks<2; ks++){
    unsigned kA = ks*32;
    unsigned kB = ks*16*(PCHB*2);
    unsigned af[4][4], bh[8], bl[8];
    ldsm4t(&bh[0], bH + kB);
    ldsm4t(&bh[4], bH + kB + 32);
    #pragma unroll
    for (int mi=0;mi<4;mi++) ldsm4(af[mi], aH + mi*(16*PCHB*2) + kA);
    #pragma unroll
    for (int mi=0;mi<4;mi++)
      #pragma unroll
      for (int ni=0;ni<4;ni++) mma16816(acc[mi][ni], af[mi], &bh[ni*2]);
    ldsm4t(&bl[0], bL + kB);
    ldsm4t(&bl[4], bL + kB + 32);
    #pragma unroll
    for (int mi=0;mi<4;mi++)
      #pragma unroll
      for (int ni=0;ni<4;ni++) mma16816(acc[mi][ni], af[mi], &bl[ni*2]);
    #pragma unroll
    for (int mi=0;mi<4;mi++) ldsm4(af[mi], aL + mi*(16*PCHB*2) + kA);
    #pragma unroll
    for (int mi=0;mi<4;mi++)
      #pragma unroll
      for (int ni=0;ni<4;ni++) mma16816(acc[mi][ni], af[mi], &bh[ni*2]);
  }
}
// 3-pass hi/lo mma over K=32: warp tile 64x16 (fused fwd-DFT)
__device__ __forceinline__ void mma_stage2(unsigned aH, unsigned aL,
    unsigned bH, unsigned bL, float (&acc)[4][2][4]){
  #pragma unroll
  for (int ks=0; ks<2; ks++){
    unsigned kA = ks*32;
    unsigned kB = ks*16*(PCHB*2);
    unsigned af[4][4], bh[4], bl[4];
    ldsm4t(&bh[0], bH + kB);
    #pragma unroll
    for (int mi=0;mi<4;mi++) ldsm4(af[mi], aH + mi*(16*PCHA*2) + kA);
    #pragma unroll
    for (int mi=0;mi<4;mi++)
      #pragma unroll
      for (int ni=0;ni<2;ni++) mma16816(acc[mi][ni], af[mi], &bh[ni*2]);
    ldsm4t(&bl[0], bL + kB);
    #pragma unroll
    for (int mi=0;mi<4;mi++)
      #pragma unroll
      for (int ni=0;ni<2;ni++) mma16816(acc[mi][ni], af[mi], &bl[ni*2]);
    #pragma unroll
    for (int mi=0;mi<4;mi++) ldsm4(af[mi], aL + mi*(16*PCHA*2) + kA);
    #pragma unroll
    for (int mi=0;mi<4;mi++)
      #pragma unroll
      for (int ni=0;ni<2;ni++) mma16816(acc[mi][ni], af[mi], &bh[ni*2]);
  }
}

// ---- basis tables ----
__global__ void k_basis(){
  int idx = blockIdx.x*256 + threadIdx.x;
  if (idx >= MD*NN) return;
  int m = idx >> 13, n = idx & (NN-1);
  int p = (m*n) & (NN-1);
  float s, c;
  sincospif((float)p * (1.0f/4096.0f), &s, &c);
  bf ch,cl,sh,sl;
  f2bb(c,ch,cl); f2bb(s,sh,sl);
  int chn = n>>5, off = n&31;
  g_FblkH[(size_t)(chn*64 + m)*32 + off]      = ch;
  g_FblkL[(size_t)(chn*64 + m)*32 + off]      = cl;
  g_FblkH[(size_t)(chn*64 + 32 + m)*32 + off] = sh;
  g_FblkL[(size_t)(chn*64 + 32 + m)*32 + off] = sl;
  g_FnmH[(size_t)n*64 + m]      = ch;
  g_FnmL[(size_t)n*64 + m]      = cl;
  g_FnmH[(size_t)n*64 + 32 + m] = sh;
  g_FnmL[(size_t)n*64 + 32 + m] = sl;
}

// ---- transpose spectral weights: coalesced ----
__global__ void k_spec_t(const float* __restrict__ wr, const float* __restrict__ wi){
  int idx = blockIdx.x*256 + threadIdx.x;   // over [l][i][o]
  if (idx >= NL*WD*WD) return;
  int o = idx & 127;
  int i = (idx >> 7) & 127;
  int l = idx >> 14;
  const float* sr = wr + (size_t)idx*MD;
  const float* si = wi + (size_t)idx*MD;
  size_t dbase = ((size_t)l*MD*WD + i)*WD + o;
  #pragma unroll
  for (int mq=0; mq<8; mq++){
    float4 vr = *(const float4*)&sr[mq*4];
    float4 vi = *(const float4*)&si[mq*4];
    g_wrT[dbase + (size_t)(mq*4+0)*WD*WD] = vr.x;
    g_wrT[dbase + (size_t)(mq*4+1)*WD*WD] = vr.y;
    g_wrT[dbase + (size_t)(mq*4+2)*WD*WD] = vr.z;
    g_wrT[dbase + (size_t)(mq*4+3)*WD*WD] = vr.w;
    g_wiT[dbase + (size_t)(mq*4+0)*WD*WD] = vi.x;
    g_wiT[dbase + (size_t)(mq*4+1)*WD*WD] = vi.y;
    g_wiT[dbase + (size_t)(mq*4+2)*WD*WD] = vi.z;
    g_wiT[dbase + (size_t)(mq*4+3)*WD*WD] = vi.w;
  }
}

// ---- convert skip_w and fc1_w to bf16 hi/lo ----
__global__ void k_prep(const float* __restrict__ skw, const float* __restrict__ w1){
  int idx = blockIdx.x*256 + threadIdx.x;
  if (idx < NL*WD*WD){
    bf h,l; f2bb(skw[idx],h,l);
    g_skwH[idx]=h; g_skwL[idx]=l;
  }
  if (idx < WD*WD){
    bf h,l; f2bb(w1[idx],h,l);
    g_w1H[idx]=h; g_w1L[idx]=l;
  }
}

// ---- fc0 ----
__global__ void k_fc0(const float* __restrict__ x, const float* __restrict__ w,
                      const float* __restrict__ bb){
  int idx = blockIdx.x*256 + threadIdx.x;
  int base = idx*8;
  int c = base & 127; int bn = base >> 7;
  float xv = x[bn];
  float4 w0 = *(const float4*)&w[c], w1 = *(const float4*)&w[c+4];
  float4 b0 = *(const float4*)&bb[c], b1 = *(const float4*)&bb[c+4];
  float v[8] = { xv*w0.x+b0.x, xv*w0.y+b0.y, xv*w0.z+b0.z, xv*w0.w+b0.w,
                 xv*w1.x+b1.x, xv*w1.y+b1.y, xv*w1.z+b1.z, xv*w1.w+b1.w };
  __nv_bfloat162 hh[4], ll[4];
  #pragma unroll
  for (int q=0;q<4;q++){
    bf h0,l0,h1,l1; f2bb(v[q*2],h0,l0); f2bb(v[q*2+1],h1,l1);
    hh[q] = __nv_bfloat162(h0,h1); ll[q] = __nv_bfloat162(l0,l1);
  }
  *(uint4*)&g_hh0[base] = *(uint4*)hh;
  *(uint4*)&g_hl0[base] = *(uint4*)ll;
}

// ---- layer-0 forward DFT of x (rank-1), table-based ----
__global__ __launch_bounds__(256) void k_fwd0(const float* __restrict__ x){
  int r = blockIdx.x, b = blockIdx.y, t = threadIdx.x;
  const float* xb = x + (size_t)b*NN;
  float s = 0.f;
  for (int n = t; n < NN; n += 256){
    size_t fi = (size_t)((n>>5)*64 + r)*32 + (n&31);
    float F = __bfloat162float(g_FblkH[fi]) + __bfloat162float(g_FblkL[fi]);
    s += F * xb[n];
  }
  __shared__ float red[256];
  red[t] = s; __syncthreads();
  for (int o=128;o>0;o>>=1){ if (t<o) red[t]+=red[t+o]; __syncthreads(); }
  if (t==0) g_X0[b*64+r] = red[0];
}

// ---- fused reduce + spectral mix; Y as bf16 hi/lo [b][j][o], sign folded ----
__global__ __launch_bounds__(128) void k_mix(int l, const float* __restrict__ fc0w,
                                             const float* __restrict__ fc0b){
  int m = blockIdx.x, b = blockIdx.y;
  int o = threadIdx.x;
  __shared__ float xr[128], xs[128];
  float sr, ss;
  if (l == 0){
    float xc = g_X0[b*64+m], xsn = g_X0[b*64+MD+m];
    float w = fc0w[o];
    sr = xc*w + (m==0 ? (float)NN*fc0b[o] : 0.f);
    ss = xsn*w;
  } else {
    sr = 0.f; ss = 0.f;
    #pragma unroll 8
    for (int c=0;c<64;c++){
      const float* p = g_Xp + (size_t)(b*64+c)*64*WD;
      sr += p[m*WD + o];
      ss += p[(MD+m)*WD + o];
    }
  }
  xr[o]=sr; xs[o]=ss;
  __syncthreads();
  const float* wr = g_wrT + ((size_t)l*MD + m)*WD*WD + o;
  const float* wi = g_wiT + ((size_t)l*MD + m)*WD*WD + o;
  float yr=0.f, yi=0.f;
  #pragma unroll 8
  for (int i=0;i<WD;i++){
    float a = xr[i], s = xs[i];
    float r = wr[(size_t)i*WD], q = wi[(size_t)i*WD];
    yr += a*r + s*q;
    yi += a*q - s*r;
  }
  float alpha = (m==0) ? (1.0f/NN) : (2.0f/NN);
  bf h0,l0,h1,l1;
  f2bb(alpha*yr, h0, l0);
  f2bb(-alpha*yi, h1, l1);
  g_YbH[(size_t)(b*64+m)*WD+o]    = h0;
  g_YbL[(size_t)(b*64+m)*WD+o]    = l0;
  g_YbH[(size_t)(b*64+MD+m)*WD+o] = h1;
  g_YbL[(size_t)(b*64+MD+m)*WD+o] = l1;
}

// ---- fused layer: h_new = gelu?(h@skip_w + irfft(Y) + skip_b), K=192;
//      dofwd: forward-DFT of tile -> g_Xp; dohead: fc1/gelu/fc2 from tile ----
__global__ __launch_bounds__(256,2) void k_layer(
      const bf* __restrict__ hh, const bf* __restrict__ hl,
      const float* __restrict__ skb,
      bf* __restrict__ ohh, bf* __restrict__ ohl, int l, int dogelu, int dofwd,
      int dohead, const float* __restrict__ b1v, const float* __restrict__ w2,
      const float* __restrict__ b2v, float* __restrict__ outp){
  extern __shared__ char smem[];
  __shared__ float red2[4][128];
  unsigned sb = (unsigned)__cvta_generic_to_shared(smem);
  const unsigned oAH=0, oAL=20480, oBH=40960, oBL=58368;
  const unsigned oHTH=0, oHTL=34816, oA2=69632;
  const unsigned oHB=69632, oHBL=87040;
  int b = blockIdx.y;
  int bx = blockIdx.x;
  int n0 = bx * 128;
  int tid = threadIdx.x, wid = tid>>5, lane = tid&31, g = lane>>2, tg = lane&3;
  int m_base = (wid>>2)*64, n_base = (wid&3)*32;
  int r8 = (lane&7) + 8*((lane>>3)&1);
  int c8 = 8*(lane>>4);
  unsigned laneA = (unsigned)(r8*PCHA + c8)*2;
  unsigned laneB = (unsigned)(r8*PCHB + c8)*2;
  float acc[4][4][4];
  #pragma unroll
  for (int mi=0;mi<4;mi++)
    #pragma unroll
    for (int ni=0;ni<4;ni++)
      #pragma unroll
      for (int q=0;q<4;q++) acc[mi][ni][q]=0.f;

  #define LAY_FILL(s) { \
    int st = (s)&1; int k0 = (s)*32; \
    unsigned aH = sb + oAH + st*10240, aL = sb + oAL + st*10240; \
    unsigned bH = sb + oBH + st*8704,  bL = sb + oBL + st*8704; \
    _Pragma("unroll") \
    for (int j=0;j<2;j++){ \
      int idx = tid + j*256; int row = idx>>2, q = idx&3; \
      const bf *sH, *sL; \
      if (k0 < 128){ \
        size_t off = ((size_t)b*NN + n0 + row)*WD + k0 + q*8; \
        sH = hh + off; sL = hl + off; \
      } else { \
        size_t off = (size_t)(n0+row)*64 + (k0-128) + q*8; \
        sH = g_FnmH + off; sL = g_FnmL + off; \
      } \
      cpa16(aH + row*(PCHA*2) + q*16, sH); \
      cpa16(aL + row*(PCHA*2) + q*16, sL); \
    } \
    _Pragma("unroll") \
    for (int j=0;j<2;j++){ \
      int idx = tid + j*256; int row = idx>>4, q = idx&15; \
      const bf *sH, *sL; \
      if (k0 < 128){ \
        size_t off = (size_t)l*16384 + (size_t)(k0+row)*WD + q*8; \
        sH = g_skwH + off; sL = g_skwL + off; \
      } else { \
        size_t off = (size_t)b*8192 + (size_t)(k0-128+row)*WD + q*8; \
        sH = g_YbH + off; sL = g_YbL + off; \
      } \
      cpa16(bH + row*(PCHB*2) + q*16, sH); \
      cpa16(bL + row*(PCHB*2) + q*16, sL); \
    } }

  LAY_FILL(0); CP_COMMIT;
  for (int i=0;i<6;i++){
    CP_WAIT; __syncthreads();
    if (i<5){ LAY_FILL(i+1); CP_COMMIT; }
    int st = i&1;
    mma_stage(sb+oAH+st*10240 + (unsigned)m_base*(PCHA*2) + laneA,
              sb+oAL+st*10240 + (unsigned)m_base*(PCHA*2) + laneA,
              sb+oBH+st*8704 + (unsigned)n_base*2 + laneB,
              sb+oBL+st*8704 + (unsigned)n_base*2 + laneB, acc);
  }
  #undef LAY_FILL
  __syncthreads();   // all warps done reading main smem before reuse

  // epilogue: bias(+gelu); store to gmem (unless dohead); stash tile
  bf* htH = (bf*)(smem + oHTH);
  bf* htL = (bf*)(smem + oHTL);
  int dostash = dofwd | dohead;
  #pragma unroll
  for (int ni=0;ni<4;ni++){
    int col = n_base + ni*8 + tg*2;
    float bia0 = skb[col], bia1 = skb[col+1];
    #pragma unroll
    for (int mi=0;mi<4;mi++){
      int rl = m_base + mi*16 + g;
      int r0 = n0 + rl;
      float v0=acc[mi][ni][0]+bia0, v1=acc[mi][ni][1]+bia1;
      float v2=acc[mi][ni][2]+bia0, v3=acc[mi][ni][3]+bia1;
      if (dogelu){ v0=gelu_f(v0); v1=gelu_f(v1); v2=gelu_f(v2); v3=gelu_f(v3); }
      bf h0,l0,h1,l1;
      f2bb(v0,h0,l0); f2bb(v1,h1,l1);
      if (!dohead){
        *(__nv_bfloat162*)&ohh[((size_t)b*NN + r0)*WD + col] = __nv_bfloat162(h0,h1);
        *(__nv_bfloat162*)&ohl[((size_t)b*NN + r0)*WD + col] = __nv_bfloat162(l0,l1);
      }
      if (dostash){
        *(__nv_bfloat162*)&htH[(size_t)rl*PCHB + col] = __nv_bfloat162(h0,h1);
        *(__nv_bfloat162*)&htL[(size_t)rl*PCHB + col] = __nv_bfloat162(l0,l1);
      }
      f2bb(v2,h0,l0); f2bb(v3,h1,l1);
      if (!dohead){
        *(__nv_bfloat162*)&ohh[((size_t)b*NN + r0 + 8)*WD + col] = __nv_bfloat162(h0,h1);
        *(__nv_bfloat162*)&ohl[((size_t)b*NN + r0 + 8)*WD + col] = __nv_bfloat162(l0,l1);
      }
      if (dostash){
        *(__nv_bfloat162*)&htH[(size_t)(rl+8)*PCHB + col] = __nv_bfloat162(h0,h1);
        *(__nv_bfloat162*)&htL[(size_t)(rl+8)*PCHB + col] = __nv_bfloat162(l0,l1);
      }
    }
  }
  __syncthreads();
  if (dofwd){
    // GEMM2: Xp[64 r][128 c] = F_chunk x h_tile (K=128 in 4 stages)
    float acc2[4][2][4];
    #pragma unroll
    for (int mi=0;mi<4;mi++)
      #pragma unroll
      for (int ni=0;ni<2;ni++)
        #pragma unroll
        for (int q=0;q<4;q++) acc2[mi][ni][q]=0.f;

    #define A2_FILL(s) { \
      int st = (s)&1; \
      unsigned aH = sb + oA2 + st*10240, aL = aH + 5120; \
      const bf* srcH = g_FblkH + (size_t)(bx*4 + (s))*2048; \
      const bf* srcL = g_FblkL + (size_t)(bx*4 + (s))*2048; \
      { int row = tid>>2, q = tid&3; \
        cpa16(aH + row*(PCHA*2) + q*16, srcH + tid*8); \
        cpa16(aL + row*(PCHA*2) + q*16, srcL + tid*8); } }

    A2_FILL(0); CP_COMMIT;
    unsigned bHbase = sb + oHTH + (unsigned)(wid*16)*2 + laneB;
    unsigned bLbase = sb + oHTL + (unsigned)(wid*16)*2 + laneB;
    for (int s=0;s<4;s++){
      CP_WAIT; __syncthreads();
      if (s<3){ A2_FILL(s+1); CP_COMMIT; }
      int st = s&1;
      mma_stage2(sb + oA2 + st*10240 + laneA,
                 sb + oA2 + st*10240 + 5120 + laneA,
                 bHbase + (unsigned)(s*32)*(PCHB*2),
                 bLbase + (unsigned)(s*32)*(PCHB*2), acc2);
    }
    #undef A2_FILL

    float* dst = g_Xp + (size_t)(b*64 + bx)*64*WD;
    #pragma unroll
    for (int ni=0;ni<2;ni++){
      int col = wid*16 + ni*8 + tg*2;
      #pragma unroll
      for (int mi=0;mi<4;mi++){
        int r0 = mi*16 + g;
        *(float2*)&dst[r0*WD+col]     = make_float2(acc2[mi][ni][0], acc2[mi][ni][1]);
        *(float2*)&dst[(r0+8)*WD+col] = make_float2(acc2[mi][ni][2], acc2[mi][ni][3]);
      }
    }
  }
  if (dohead){
    // head GEMM: fc1 over the stashed tile (A pitch PCHB), B = w1 hi/lo, K=128
    float acc3[4][4][4];
    #pragma unroll
    for (int mi=0;mi<4;mi++)
      #pragma unroll
      for (int ni=0;ni<4;ni++)
        #pragma unroll
        for (int q=0;q<4;q++) acc3[mi][ni][q]=0.f;

    #define HB_FILL(s) { \
      int st = (s)&1; int k0 = (s)*32; \
      unsigned bH = sb + oHB + st*8704, bL = sb + oHBL + st*8704; \
      _Pragma("unroll") \
      for (int j=0;j<2;j++){ \
        int idx = tid + j*256; int row = idx>>4, q = idx&15; \
        size_t off = (size_t)(k0+row)*WD + q*8; \
        cpa16(bH + row*(PCHB*2) + q*16, g_w1H + off); \
        cpa16(bL + row*(PCHB*2) + q*16, g_w1L + off); \
      } }

    HB_FILL(0); CP_COMMIT;
    unsigned aHb = sb + oHTH + (unsigned)m_base*(PCHB*2) + laneB;
    unsigned aLb = sb + oHTL + (unsigned)m_base*(PCHB*2) + laneB;
    for (int s=0;s<4;s++){
      CP_WAIT; __syncthreads();
      if (s<3){ HB_FILL(s+1); CP_COMMIT; }
      int st = s&1;
      mma_stageHD(aHb + (unsigned)(s*64), aLb + (unsigned)(s*64),
                  sb+oHB+st*8704 + (unsigned)n_base*2 + laneB,
                  sb+oHBL+st*8704 + (unsigned)n_base*2 + laneB, acc3);
    }
    #undef HB_FILL

    float s2[4][2];
    #pragma unroll
    for (int mi=0;mi<4;mi++){ s2[mi][0]=0.f; s2[mi][1]=0.f; }
    #pragma unroll
    for (int ni=0;ni<4;ni++){
      int col = n_base + ni*8 + tg*2;
      float bia0=b1v[col], bia1=b1v[col+1];
      float w20=w2[col],  w21=w2[col+1];
      #pragma unroll
      for (int mi=0;mi<4;mi++){
        s2[mi][0] += gelu_f(acc3[mi][ni][0]+bia0)*w20 + gelu_f(acc3[mi][ni][1]+bia1)*w21;
        s2[mi][1] += gelu_f(acc3[mi][ni][2]+bia0)*w20 + gelu_f(acc3[mi][ni][3]+bia1)*w21;
      }
    }
    #pragma unroll
    for (int mi=0;mi<4;mi++){
      #pragma unroll
      for (int q=0;q<2;q++){
        s2[mi][q] += __shfl_xor_sync(0xffffffffu, s2[mi][q], 1);
        s2[mi][q] += __shfl_xor_sync(0xffffffffu, s2[mi][q], 2);
      }
    }
    __syncthreads();
    if (tg == 0){
      int wn = wid & 3;
      #pragma unroll
      for (int mi=0;mi<4;mi++){
        red2[wn][m_base+mi*16+g]   = s2[mi][0];
        red2[wn][m_base+mi*16+g+8] = s2[mi][1];
      }
    }
    __syncthreads();
    if (tid < 128)
      outp[(size_t)b*NN + n0 + tid] =
        red2[0][tid]+red2[1][tid]+red2[2][tid]+red2[3][tid] + b2v[0];
  }
}

extern "C" void kernel_launch(void* const* d_in, const int* in_sizes, int n_in,
                              void* d_out, int out_size){
  const float* x       = (const float*)d_in[0];
  const float* fc0_w   = (const float*)d_in[1];
  const float* fc0_b   = (const float*)d_in[2];
  const float* spec_wr = (const float*)d_in[3];
  const float* spec_wi = (const float*)d_in[4];
  const float* skip_w  = (const float*)d_in[5];
  const float* skip_b  = (const float*)d_in[6];
  const float* fc1_w   = (const float*)d_in[7];
  const float* fc1_b   = (const float*)d_in[8];
  const float* fc2_w   = (const float*)d_in[9];
  const float* fc2_b   = (const float*)d_in[10];
  float* out = (float*)d_out;
  (void)in_sizes; (void)n_in; (void)out_size;

  static int init_done = 0;
  static cudaStream_t st[3];
  static cudaEvent_t evRoot, evD[3];
  if (!init_done){
    cudaFuncSetAttribute(k_layer, cudaFuncAttributeMaxDynamicSharedMemorySize, 104448);
    for (int i=0;i<3;i++) cudaStreamCreateWithFlags(&st[i], cudaStreamNonBlocking);
    cudaEventCreateWithFlags(&evRoot, cudaEventDisableTiming);
    for (int i=0;i<3;i++) cudaEventCreateWithFlags(&evD[i], cudaEventDisableTiming);
    init_done = 1;
  }

  void *ph0, *pl0, *ph1, *pl1;
  cudaGetSymbolAddress(&ph0, g_hh0);
  cudaGetSymbolAddress(&pl0, g_hl0);
  cudaGetSymbolAddress(&ph1, g_hh1);
  cudaGetSymbolAddress(&pl1, g_hl1);
  bf* hinH = (bf*)ph0; bf* hinL = (bf*)pl0;
  bf* houtH = (bf*)ph1; bf* houtL = (bf*)pl1;

  // fork setup work onto side streams (captured via event fork/join)
  cudaEventRecord(evRoot, 0);
  cudaStreamWaitEvent(st[0], evRoot, 0);
  k_basis<<<(MD*NN + 255)/256, 256, 0, st[0]>>>();
  k_fwd0<<<dim3(64, Bq), 256, 0, st[0]>>>(x);
  cudaEventRecord(evD[0], st[0]);
  cudaStreamWaitEvent(st[1], evRoot, 0);
  k_spec_t<<<(NL*WD*WD + 255)/256, 256, 0, st[1]>>>(spec_wr, spec_wi);
  k_prep<<<(NL*WD*WD + 255)/256, 256, 0, st[1]>>>(skip_w, fc1_w);
  cudaEventRecord(evD[1], st[1]);
  cudaStreamWaitEvent(st[2], evRoot, 0);
  k_fc0<<<(Bq*NN*WD/8)/256, 256, 0, st[2]>>>(x, fc0_w, fc0_b);
  cudaEventRecord(evD[2], st[2]);
  cudaStreamWaitEvent(0, evD[0], 0);
  cudaStreamWaitEvent(0, evD[1], 0);
  cudaStreamWaitEvent(0, evD[2], 0);

  for (int l=0; l<NL; l++){
    int last = (l == NL-1);
    k_mix<<<dim3(MD, Bq), 128>>>(l, fc0_w, fc0_b);
    k_layer<<<dim3(NN/128, Bq), 256, 104448>>>(hinH, hinL,
        skip_b + (size_t)l*WD, houtH, houtL, l,
        last ? 0 : 1, last ? 0 : 1,
        last ? 1 : 0, fc1_b, fc2_w, fc2_b, out);
    bf* t;
    t = hinH; hinH = houtH; houtH = t;
    t = hinL; hinL = houtL; houtL = t;
  }
}

// round 17
// speedup vs baseline: 1.0755x; 1.0755x over previous
#include <cuda_runtime.h>
#include <cuda_bf16.h>
#include <math.h>

#define Bq 16
#define NN 8192
#define WD 128
#define MD 32
#define NL 4
#define PCHA 40        // A smem pitch (bf16): 16B-aligned rows, conflict-free ldmatrix
#define PCHB 136       // B smem pitch

typedef __nv_bfloat16 bf;

// ---- static device scratch ----
__device__ __align__(16) bf g_hh0[Bq*NN*WD];
__device__ __align__(16) bf g_hl0[Bq*NN*WD];
__device__ __align__(16) bf g_hh1[Bq*NN*WD];
__device__ __align__(16) bf g_hl1[Bq*NN*WD];
__device__ __align__(16) bf g_FblkH[64*NN];   // [n-chunk32][64 r][32]
__device__ __align__(16) bf g_FblkL[64*NN];
__device__ __align__(16) bf g_FnmH[NN*64];    // [n][r]
__device__ __align__(16) bf g_FnmL[NN*64];
__device__ __align__(16) bf g_skwH[NL*WD*WD]; // [l][k][o]
__device__ __align__(16) bf g_skwL[NL*WD*WD];
__device__ __align__(16) bf g_w1H[WD*WD];     // [k][o]
__device__ __align__(16) bf g_w1L[WD*WD];
__device__ __align__(16) bf g_YbH[Bq*64*WD];  // [b][j][o]: j<32 Yr', j>=32 -Yi'
__device__ __align__(16) bf g_YbL[Bq*64*WD];
__device__ float g_Xp[Bq*64*64*WD];           // split-K partials, 64 chunks
__device__ float g_X0[Bq*64];                 // layer-0 x-DFT
__device__ float g_wrT[NL*MD*WD*WD];
__device__ float g_wiT[NL*MD*WD*WD];

__device__ __forceinline__ void f2bb(float x, bf &h, bf &l){
  h = __float2bfloat16(x);
  l = __float2bfloat16(x - __bfloat162float(h));
}
__device__ __forceinline__ float gelu_f(float v){
  return 0.5f*v*(1.0f + erff(v*0.70710678118654752f));
}
__device__ __forceinline__ void mma16816(float* d, const unsigned* a, const unsigned* b){
  asm volatile("mma.sync.aligned.m16n8k16.row.col.f32.bf16.bf16.f32 "
    "{%0,%1,%2,%3},{%4,%5,%6,%7},{%8,%9},{%0,%1,%2,%3};\n"
    : "+f"(d[0]),"+f"(d[1]),"+f"(d[2]),"+f"(d[3])
    : "r"(a[0]),"r"(a[1]),"r"(a[2]),"r"(a[3]),"r"(b[0]),"r"(b[1]));
}
__device__ __forceinline__ void ldsm4(unsigned* d, unsigned addr){
  asm volatile("ldmatrix.sync.aligned.m8n8.x4.shared.b16 {%0,%1,%2,%3}, [%4];"
    : "=r"(d[0]),"=r"(d[1]),"=r"(d[2]),"=r"(d[3]) : "r"(addr));
}
__device__ __forceinline__ void ldsm4t(unsigned* d, unsigned addr){
  asm volatile("ldmatrix.sync.aligned.m8n8.x4.trans.shared.b16 {%0,%1,%2,%3}, [%4];"
    : "=r"(d[0]),"=r"(d[1]),"=r"(d[2]),"=r"(d[3]) : "r"(addr));
}
__device__ __forceinline__ void cpa16(unsigned dst, const void* src){
  asm volatile("cp.async.cg.shared.global [%0], [%1], 16;" :: "r"(dst), "l"(src));
}
#define CP_COMMIT asm volatile("cp.async.commit_group;")
#define CP_WAIT   asm volatile("cp.async.wait_group 0;")

// 3-pass hi/lo mma over K=32: warp tile 64x32 (A pitch PCHA)
__device__ __forceinline__ void mma_stage(unsigned aH, unsigned aL,
    unsigned bH, unsigned bL, float (&acc)[4][4][4]){
  #pragma unroll
  for (int ks=0; ks<2; ks++){
    unsigned kA = ks*32;
    unsigned kB = ks*16*(PCHB*2);
    unsigned af[4][4], bh[8], bl[8];
    ldsm4t(&bh[0], bH + kB);
    ldsm4t(&bh[4], bH + kB + 32);
    #pragma unroll
    for (int mi=0;mi<4;mi++) ldsm4(af[mi], aH + mi*(16*PCHA*2) + kA);
    #pragma unroll
    for (int mi=0;mi<4;mi++)
      #pragma unroll
      for (int ni=0;ni<4;ni++) mma16816(acc[mi][ni], af[mi], &bh[ni*2]);
    ldsm4t(&bl[0], bL + kB);
    ldsm4t(&bl[4], bL + kB + 32);
    #pragma unroll
    for (int mi=0;mi<4;mi++)
      #pragma unroll
      for (int ni=0;ni<4;ni++) mma16816(acc[mi][ni], af[mi], &bl[ni*2]);
    #pragma unroll
    for (int mi=0;mi<4;mi++) ldsm4(af[mi], aL + mi*(16*PCHA*2) + kA);
    #pragma unroll
    for (int mi=0;mi<4;mi++)
      #pragma unroll
      for (int ni=0;ni<4;ni++) mma16816(acc[mi][ni], af[mi], &bh[ni*2]);
  }
}
// same but A pitch PCHB (A = stashed h tile) — fused head GEMM
__device__ __forceinline__ void mma_stageHD(unsigned aH, unsigned aL,
    unsigned bH, unsigned bL, float (&acc)[4][4][4]){
  #pragma unroll
  for (int ks=0; ks<2; ks++){
    unsigned kA = ks*32;
    unsigned kB = ks*16*(PCHB*2);
    unsigned af[4][4], bh[8], bl[8];
    ldsm4t(&bh[0], bH + kB);
    ldsm4t(&bh[4], bH + kB + 32);
    #pragma unroll
    for (int mi=0;mi<4;mi++) ldsm4(af[mi], aH + mi*(16*PCHB*2) + kA);
    #pragma unroll
    for (int mi=0;mi<4;mi++)
      #pragma unroll
      for (int ni=0;ni<4;ni++) mma16816(acc[mi][ni], af[mi], &bh[ni*2]);
    ldsm4t(&bl[0], bL + kB);
    ldsm4t(&bl[4], bL + kB + 32);
    #pragma unroll
    for (int mi=0;mi<4;mi++)
      #pragma unroll
      for (int ni=0;ni<4;ni++) mma16816(acc[mi][ni], af[mi], &bl[ni*2]);
    #pragma unroll
    for (int mi=0;mi<4;mi++) ldsm4(af[mi], aL + mi*(16*PCHB*2) + kA);
    #pragma unroll
    for (int mi=0;mi<4;mi++)
      #pragma unroll
      for (int ni=0;ni<4;ni++) mma16816(acc[mi][ni], af[mi], &bh[ni*2]);
  }
}
// 3-pass hi/lo mma over K=32: warp tile 64x16 (fused fwd-DFT)
__device__ __forceinline__ void mma_stage2(unsigned aH, unsigned aL,
    unsigned bH, unsigned bL, float (&acc)[4][2][4]){
  #pragma unroll
  for (int ks=0; ks<2; ks++){
    unsigned kA = ks*32;
    unsigned kB = ks*16*(PCHB*2);
    unsigned af[4][4], bh[4], bl[4];
    ldsm4t(&bh[0], bH + kB);
    #pragma unroll
    for (int mi=0;mi<4;mi++) ldsm4(af[mi], aH + mi*(16*PCHA*2) + kA);
    #pragma unroll
    for (int mi=0;mi<4;mi++)
      #pragma unroll
      for (int ni=0;ni<2;ni++) mma16816(acc[mi][ni], af[mi], &bh[ni*2]);
    ldsm4t(&bl[0], bL + kB);
    #pragma unroll
    for (int mi=0;mi<4;mi++)
      #pragma unroll
      for (int ni=0;ni<2;ni++) mma16816(acc[mi][ni], af[mi], &bl[ni*2]);
    #pragma unroll
    for (int mi=0;mi<4;mi++) ldsm4(af[mi], aL + mi*(16*PCHA*2) + kA);
    #pragma unroll
    for (int mi=0;mi<4;mi++)
      #pragma unroll
      for (int ni=0;ni<2;ni++) mma16816(acc[mi][ni], af[mi], &bh[ni*2]);
  }
}

// ---- basis tables ----
__global__ void k_basis(){
  int idx = blockIdx.x*256 + threadIdx.x;
  if (idx >= MD*NN) return;
  int m = idx >> 13, n = idx & (NN-1);
  int p = (m*n) & (NN-1);
  float s, c;
  sincospif((float)p * (1.0f/4096.0f), &s, &c);
  bf ch,cl,sh,sl;
  f2bb(c,ch,cl); f2bb(s,sh,sl);
  int chn = n>>5, off = n&31;
  g_FblkH[(size_t)(chn*64 + m)*32 + off]      = ch;
  g_FblkL[(size_t)(chn*64 + m)*32 + off]      = cl;
  g_FblkH[(size_t)(chn*64 + 32 + m)*32 + off] = sh;
  g_FblkL[(size_t)(chn*64 + 32 + m)*32 + off] = sl;
  g_FnmH[(size_t)n*64 + m]      = ch;
  g_FnmL[(size_t)n*64 + m]      = cl;
  g_FnmH[(size_t)n*64 + 32 + m] = sh;
  g_FnmL[(size_t)n*64 + 32 + m] = sl;
}

// ---- transpose spectral weights: coalesced ----
__global__ void k_spec_t(const float* __restrict__ wr, const float* __restrict__ wi){
  int idx = blockIdx.x*256 + threadIdx.x;   // over [l][i][o]
  if (idx >= NL*WD*WD) return;
  int o = idx & 127;
  int i = (idx >> 7) & 127;
  int l = idx >> 14;
  const float* sr = wr + (size_t)idx*MD;
  const float* si = wi + (size_t)idx*MD;
  size_t dbase = ((size_t)l*MD*WD + i)*WD + o;
  #pragma unroll
  for (int mq=0; mq<8; mq++){
    float4 vr = *(const float4*)&sr[mq*4];
    float4 vi = *(const float4*)&si[mq*4];
    g_wrT[dbase + (size_t)(mq*4+0)*WD*WD] = vr.x;
    g_wrT[dbase + (size_t)(mq*4+1)*WD*WD] = vr.y;
    g_wrT[dbase + (size_t)(mq*4+2)*WD*WD] = vr.z;
    g_wrT[dbase + (size_t)(mq*4+3)*WD*WD] = vr.w;
    g_wiT[dbase + (size_t)(mq*4+0)*WD*WD] = vi.x;
    g_wiT[dbase + (size_t)(mq*4+1)*WD*WD] = vi.y;
    g_wiT[dbase + (size_t)(mq*4+2)*WD*WD] = vi.z;
    g_wiT[dbase + (size_t)(mq*4+3)*WD*WD] = vi.w;
  }
}

// ---- convert skip_w and fc1_w to bf16 hi/lo ----
__global__ void k_prep(const float* __restrict__ skw, const float* __restrict__ w1){
  int idx = blockIdx.x*256 + threadIdx.x;
  if (idx < NL*WD*WD){
    bf h,l; f2bb(skw[idx],h,l);
    g_skwH[idx]=h; g_skwL[idx]=l;
  }
  if (idx < WD*WD){
    bf h,l; f2bb(w1[idx],h,l);
    g_w1H[idx]=h; g_w1L[idx]=l;
  }
}

// ---- fc0 ----
__global__ void k_fc0(const float* __restrict__ x, const float* __restrict__ w,
                      const float* __restrict__ bb){
  int idx = blockIdx.x*256 + threadIdx.x;
  int base = idx*8;
  int c = base & 127; int bn = base >> 7;
  float xv = x[bn];
  float4 w0 = *(const float4*)&w[c], w1 = *(const float4*)&w[c+4];
  float4 b0 = *(const float4*)&bb[c], b1 = *(const float4*)&bb[c+4];
  float v[8] = { xv*w0.x+b0.x, xv*w0.y+b0.y, xv*w0.z+b0.z, xv*w0.w+b0.w,
                 xv*w1.x+b1.x, xv*w1.y+b1.y, xv*w1.z+b1.z, xv*w1.w+b1.w };
  __nv_bfloat162 hh[4], ll[4];
  #pragma unroll
  for (int q=0;q<4;q++){
    bf h0,l0,h1,l1; f2bb(v[q*2],h0,l0); f2bb(v[q*2+1],h1,l1);
    hh[q] = __nv_bfloat162(h0,h1); ll[q] = __nv_bfloat162(l0,l1);
  }
  *(uint4*)&g_hh0[base] = *(uint4*)hh;
  *(uint4*)&g_hl0[base] = *(uint4*)ll;
}

// ---- layer-0 forward DFT of x (rank-1), table-based ----
__global__ __launch_bounds__(256) void k_fwd0(const float* __restrict__ x){
  int r = blockIdx.x, b = blockIdx.y, t = threadIdx.x;
  const float* xb = x + (size_t)b*NN;
  float s = 0.f;
  for (int n = t; n < NN; n += 256){
    size_t fi = (size_t)((n>>5)*64 + r)*32 + (n&31);
    float F = __bfloat162float(g_FblkH[fi]) + __bfloat162float(g_FblkL[fi]);
    s += F * xb[n];
  }
  __shared__ float red[256];
  red[t] = s; __syncthreads();
  for (int o=128;o>0;o>>=1){ if (t<o) red[t]+=red[t+o]; __syncthreads(); }
  if (t==0) g_X0[b*64+r] = red[0];
}

// ---- fused reduce + spectral mix; 256 threads, 2-way latency split ----
__global__ __launch_bounds__(256) void k_mix(int l, const float* __restrict__ fc0w,
                                             const float* __restrict__ fc0b){
  int m = blockIdx.x, b = blockIdx.y;
  int tid = threadIdx.x;
  int half = tid >> 7, o = tid & 127;
  __shared__ float xr[128], xs[128];
  __shared__ float xrP[2][128], xsP[2][128];
  __shared__ float yrP[2][128], yiP[2][128];
  if (l == 0){
    if (half == 0){
      float xc = g_X0[b*64+m], xsn = g_X0[b*64+MD+m];
      float w = fc0w[o];
      xr[o] = xc*w + (m==0 ? (float)NN*fc0b[o] : 0.f);
      xs[o] = xsn*w;
    }
  } else {
    float sr = 0.f, ss = 0.f;
    int c0 = half*32;
    #pragma unroll 8
    for (int c=c0; c<c0+32; c++){
      const float* p = g_Xp + (size_t)(b*64+c)*64*WD;
      sr += p[m*WD + o];
      ss += p[(MD+m)*WD + o];
    }
    xrP[half][o] = sr; xsP[half][o] = ss;
  }
  __syncthreads();
  if (l > 0 && half == 0){
    xr[o] = xrP[0][o] + xrP[1][o];
    xs[o] = xsP[0][o] + xsP[1][o];
  }
  __syncthreads();
  // phase 2: split the 128-i weight loop across halves
  const float* wr = g_wrT + ((size_t)l*MD + m)*WD*WD + o;
  const float* wi = g_wiT + ((size_t)l*MD + m)*WD*WD + o;
  float yr=0.f, yi=0.f;
  int i0 = half*64;
  #pragma unroll 8
  for (int i=i0; i<i0+64; i++){
    float a = xr[i], s = xs[i];
    float r = wr[(size_t)i*WD], q = wi[(size_t)i*WD];
    yr += a*r + s*q;
    yi += a*q - s*r;
  }
  yrP[half][o] = yr; yiP[half][o] = yi;
  __syncthreads();
  if (half == 0){
    float Yr = yrP[0][o] + yrP[1][o];
    float Yi = yiP[0][o] + yiP[1][o];
    float alpha = (m==0) ? (1.0f/NN) : (2.0f/NN);
    bf h0,l0,h1,l1;
    f2bb(alpha*Yr, h0, l0);
    f2bb(-alpha*Yi, h1, l1);
    g_YbH[(size_t)(b*64+m)*WD+o]    = h0;
    g_YbL[(size_t)(b*64+m)*WD+o]    = l0;
    g_YbH[(size_t)(b*64+MD+m)*WD+o] = h1;
    g_YbL[(size_t)(b*64+MD+m)*WD+o] = l1;
  }
}

// ---- fused layer: h_new = gelu?(h@skip_w + irfft(Y) + skip_b), K=192;
//      dofwd: forward-DFT of tile -> g_Xp; dohead: fc1/gelu/fc2 from tile ----
__global__ __launch_bounds__(256,2) void k_layer(
      const bf* __restrict__ hh, const bf* __restrict__ hl,
      const float* __restrict__ skb,
      bf* __restrict__ ohh, bf* __restrict__ ohl, int l, int dogelu, int dofwd,
      int dohead, const float* __restrict__ b1v, const float* __restrict__ w2,
      const float* __restrict__ b2v, float* __restrict__ outp){
  extern __shared__ char smem[];
  __shared__ float red2[4][128];
  unsigned sb = (unsigned)__cvta_generic_to_shared(smem);
  const unsigned oAH=0, oAL=20480, oBH=40960, oBL=58368;
  const unsigned oHTH=0, oHTL=34816, oA2=69632;
  const unsigned oHB=69632, oHBL=87040;
  int b = blockIdx.y;
  int bx = blockIdx.x;
  int n0 = bx * 128;
  int tid = threadIdx.x, wid = tid>>5, lane = tid&31, g = lane>>2, tg = lane&3;
  int m_base = (wid>>2)*64, n_base = (wid&3)*32;
  int r8 = (lane&7) + 8*((lane>>3)&1);
  int c8 = 8*(lane>>4);
  unsigned laneA = (unsigned)(r8*PCHA + c8)*2;
  unsigned laneB = (unsigned)(r8*PCHB + c8)*2;
  float acc[4][4][4];
  #pragma unroll
  for (int mi=0;mi<4;mi++)
    #pragma unroll
    for (int ni=0;ni<4;ni++)
      #pragma unroll
      for (int q=0;q<4;q++) acc[mi][ni][q]=0.f;

  #define LAY_FILL(s) { \
    int st = (s)&1; int k0 = (s)*32; \
    unsigned aH = sb + oAH + st*10240, aL = sb + oAL + st*10240; \
    unsigned bH = sb + oBH + st*8704,  bL = sb + oBL + st*8704; \
    _Pragma("unroll") \
    for (int j=0;j<2;j++){ \
      int idx = tid + j*256; int row = idx>>2, q = idx&3; \
      const bf *sH, *sL; \
      if (k0 < 128){ \
        size_t off = ((size_t)b*NN + n0 + row)*WD + k0 + q*8; \
        sH = hh + off; sL = hl + off; \
      } else { \
        size_t off = (size_t)(n0+row)*64 + (k0-128) + q*8; \
        sH = g_FnmH + off; sL = g_FnmL + off; \
      } \
      cpa16(aH + row*(PCHA*2) + q*16, sH); \
      cpa16(aL + row*(PCHA*2) + q*16, sL); \
    } \
    _Pragma("unroll") \
    for (int j=0;j<2;j++){ \
      int idx = tid + j*256; int row = idx>>4, q = idx&15; \
      const bf *sH, *sL; \
      if (k0 < 128){ \
        size_t off = (size_t)l*16384 + (size_t)(k0+row)*WD + q*8; \
        sH = g_skwH + off; sL = g_skwL + off; \
      } else { \
        size_t off = (size_t)b*8192 + (size_t)(k0-128+row)*WD + q*8; \
        sH = g_YbH + off; sL = g_YbL + off; \
      } \
      cpa16(bH + row*(PCHB*2) + q*16, sH); \
      cpa16(bL + row*(PCHB*2) + q*16, sL); \
    } }

  LAY_FILL(0); CP_COMMIT;
  for (int i=0;i<6;i++){
    CP_WAIT; __syncthreads();
    if (i<5){ LAY_FILL(i+1); CP_COMMIT; }
    int st = i&1;
    mma_stage(sb+oAH+st*10240 + (unsigned)m_base*(PCHA*2) + laneA,
              sb+oAL+st*10240 + (unsigned)m_base*(PCHA*2) + laneA,
              sb+oBH+st*8704 + (unsigned)n_base*2 + laneB,
              sb+oBL+st*8704 + (unsigned)n_base*2 + laneB, acc);
  }
  #undef LAY_FILL
  __syncthreads();   // all warps done reading main smem before reuse

  // epilogue: bias(+gelu); store to gmem (unless dohead); stash tile
  bf* htH = (bf*)(smem + oHTH);
  bf* htL = (bf*)(smem + oHTL);
  int dostash = dofwd | dohead;
  #pragma unroll
  for (int ni=0;ni<4;ni++){
    int col = n_base + ni*8 + tg*2;
    float bia0 = skb[col], bia1 = skb[col+1];
    #pragma unroll
    for (int mi=0;mi<4;mi++){
      int rl = m_base + mi*16 + g;
      int r0 = n0 + rl;
      float v0=acc[mi][ni][0]+bia0, v1=acc[mi][ni][1]+bia1;
      float v2=acc[mi][ni][2]+bia0, v3=acc[mi][ni][3]+bia1;
      if (dogelu){ v0=gelu_f(v0); v1=gelu_f(v1); v2=gelu_f(v2); v3=gelu_f(v3); }
      bf h0,l0,h1,l1;
      f2bb(v0,h0,l0); f2bb(v1,h1,l1);
      if (!dohead){
        *(__nv_bfloat162*)&ohh[((size_t)b*NN + r0)*WD + col] = __nv_bfloat162(h0,h1);
        *(__nv_bfloat162*)&ohl[((size_t)b*NN + r0)*WD + col] = __nv_bfloat162(l0,l1);
      }
      if (dostash){
        *(__nv_bfloat162*)&htH[(size_t)rl*PCHB + col] = __nv_bfloat162(h0,h1);
        *(__nv_bfloat162*)&htL[(size_t)rl*PCHB + col] = __nv_bfloat162(l0,l1);
      }
      f2bb(v2,h0,l0); f2bb(v3,h1,l1);
      if (!dohead){
        *(__nv_bfloat162*)&ohh[((size_t)b*NN + r0 + 8)*WD + col] = __nv_bfloat162(h0,h1);
        *(__nv_bfloat162*)&ohl[((size_t)b*NN + r0 + 8)*WD + col] = __nv_bfloat162(l0,l1);
      }
      if (dostash){
        *(__nv_bfloat162*)&htH[(size_t)(rl+8)*PCHB + col] = __nv_bfloat162(h0,h1);
        *(__nv_bfloat162*)&htL[(size_t)(rl+8)*PCHB + col] = __nv_bfloat162(l0,l1);
      }
    }
  }
  __syncthreads();
  if (dofwd){
    // GEMM2: Xp[64 r][128 c] = F_chunk x h_tile (K=128 in 4 stages)
    float acc2[4][2][4];
    #pragma unroll
    for (int mi=0;mi<4;mi++)
      #pragma unroll
      for (int ni=0;ni<2;ni++)
        #pragma unroll
        for (int q=0;q<4;q++) acc2[mi][ni][q]=0.f;

    #define A2_FILL(s) { \
      int st = (s)&1; \
      unsigned aH = sb + oA2 + st*10240, aL = aH + 5120; \
      const bf* srcH = g_FblkH + (size_t)(bx*4 + (s))*2048; \
      const bf* srcL = g_FblkL + (size_t)(bx*4 + (s))*2048; \
      { int row = tid>>2, q = tid&3; \
        cpa16(aH + row*(PCHA*2) + q*16, srcH + tid*8); \
        cpa16(aL + row*(PCHA*2) + q*16, srcL + tid*8); } }

    A2_FILL(0); CP_COMMIT;
    unsigned bHbase = sb + oHTH + (unsigned)(wid*16)*2 + laneB;
    unsigned bLbase = sb + oHTL + (unsigned)(wid*16)*2 + laneB;
    for (int s=0;s<4;s++){
      CP_WAIT; __syncthreads();
      if (s<3){ A2_FILL(s+1); CP_COMMIT; }
      int st = s&1;
      mma_stage2(sb + oA2 + st*10240 + laneA,
                 sb + oA2 + st*10240 + 5120 + laneA,
                 bHbase + (unsigned)(s*32)*(PCHB*2),
                 bLbase + (unsigned)(s*32)*(PCHB*2), acc2);
    }
    #undef A2_FILL

    float* dst = g_Xp + (size_t)(b*64 + bx)*64*WD;
    #pragma unroll
    for (int ni=0;ni<2;ni++){
      int col = wid*16 + ni*8 + tg*2;
      #pragma unroll
      for (int mi=0;mi<4;mi++){
        int r0 = mi*16 + g;
        *(float2*)&dst[r0*WD+col]     = make_float2(acc2[mi][ni][0], acc2[mi][ni][1]);
        *(float2*)&dst[(r0+8)*WD+col] = make_float2(acc2[mi][ni][2], acc2[mi][ni][3]);
      }
    }
  }
  if (dohead){
    // head GEMM: fc1 over the stashed tile (A pitch PCHB), B = w1 hi/lo, K=128
    float acc3[4][4][4];
    #pragma unroll
    for (int mi=0;mi<4;mi++)
      #pragma unroll
      for (int ni=0;ni<4;ni++)
        #pragma unroll
        for (int q=0;q<4;q++) acc3[mi][ni][q]=0.f;

    #define HB_FILL(s) { \
      int st = (s)&1; int k0 = (s)*32; \
      unsigned bH = sb + oHB + st*8704, bL = sb + oHBL + st*8704; \
      _Pragma("unroll") \
      for (int j=0;j<2;j++){ \
        int idx = tid + j*256; int row = idx>>4, q = idx&15; \
        size_t off = (size_t)(k0+row)*WD + q*8; \
        cpa16(bH + row*(PCHB*2) + q*16, g_w1H + off); \
        cpa16(bL + row*(PCHB*2) + q*16, g_w1L + off); \
      } }

    HB_FILL(0); CP_COMMIT;
    unsigned aHb = sb + oHTH + (unsigned)m_base*(PCHB*2) + laneB;
    unsigned aLb = sb + oHTL + (unsigned)m_base*(PCHB*2) + laneB;
    for (int s=0;s<4;s++){
      CP_WAIT; __syncthreads();
      if (s<3){ HB_FILL(s+1); CP_COMMIT; }
      int st = s&1;
      mma_stageHD(aHb + (unsigned)(s*64), aLb + (unsigned)(s*64),
                  sb+oHB+st*8704 + (unsigned)n_base*2 + laneB,
                  sb+oHBL+st*8704 + (unsigned)n_base*2 + laneB, acc3);
    }
    #undef HB_FILL

    float s2[4][2];
    #pragma unroll
    for (int mi=0;mi<4;mi++){ s2[mi][0]=0.f; s2[mi][1]=0.f; }
    #pragma unroll
    for (int ni=0;ni<4;ni++){
      int col = n_base + ni*8 + tg*2;
      float bia0=b1v[col], bia1=b1v[col+1];
      float w20=w2[col],  w21=w2[col+1];
      #pragma unroll
      for (int mi=0;mi<4;mi++){
        s2[mi][0] += gelu_f(acc3[mi][ni][0]+bia0)*w20 + gelu_f(acc3[mi][ni][1]+bia1)*w21;
        s2[mi][1] += gelu_f(acc3[mi][ni][2]+bia0)*w20 + gelu_f(acc3[mi][ni][3]+bia1)*w21;
      }
    }
    #pragma unroll
    for (int mi=0;mi<4;mi++){
      #pragma unroll
      for (int q=0;q<2;q++){
        s2[mi][q] += __shfl_xor_sync(0xffffffffu, s2[mi][q], 1);
        s2[mi][q] += __shfl_xor_sync(0xffffffffu, s2[mi][q], 2);
      }
    }
    __syncthreads();
    if (tg == 0){
      int wn = wid & 3;
      #pragma unroll
      for (int mi=0;mi<4;mi++){
        red2[wn][m_base+mi*16+g]   = s2[mi][0];
        red2[wn][m_base+mi*16+g+8] = s2[mi][1];
      }
    }
    __syncthreads();
    if (tid < 128)
      outp[(size_t)b*NN + n0 + tid] =
        red2[0][tid]+red2[1][tid]+red2[2][tid]+red2[3][tid] + b2v[0];
  }
}

extern "C" void kernel_launch(void* const* d_in, const int* in_sizes, int n_in,
                              void* d_out, int out_size){
  const float* x       = (const float*)d_in[0];
  const float* fc0_w   = (const float*)d_in[1];
  const float* fc0_b   = (const float*)d_in[2];
  const float* spec_wr = (const float*)d_in[3];
  const float* spec_wi = (const float*)d_in[4];
  const float* skip_w  = (const float*)d_in[5];
  const float* skip_b  = (const float*)d_in[6];
  const float* fc1_w   = (const float*)d_in[7];
  const float* fc1_b   = (const float*)d_in[8];
  const float* fc2_w   = (const float*)d_in[9];
  const float* fc2_b   = (const float*)d_in[10];
  float* out = (float*)d_out;
  (void)in_sizes; (void)n_in; (void)out_size;

  static int init_done = 0;
  static cudaStream_t st[3];
  static cudaEvent_t evRoot, evD[3];
  if (!init_done){
    cudaFuncSetAttribute(k_layer, cudaFuncAttributeMaxDynamicSharedMemorySize, 104448);
    for (int i=0;i<3;i++) cudaStreamCreateWithFlags(&st[i], cudaStreamNonBlocking);
    cudaEventCreateWithFlags(&evRoot, cudaEventDisableTiming);
    for (int i=0;i<3;i++) cudaEventCreateWithFlags(&evD[i], cudaEventDisableTiming);
    init_done = 1;
  }

  void *ph0, *pl0, *ph1, *pl1;
  cudaGetSymbolAddress(&ph0, g_hh0);
  cudaGetSymbolAddress(&pl0, g_hl0);
  cudaGetSymbolAddress(&ph1, g_hh1);
  cudaGetSymbolAddress(&pl1, g_hl1);
  bf* hinH = (bf*)ph0; bf* hinL = (bf*)pl0;
  bf* houtH = (bf*)ph1; bf* houtL = (bf*)pl1;

  // fork setup work onto side streams (captured via event fork/join)
  cudaEventRecord(evRoot, 0);
  cudaStreamWaitEvent(st[0], evRoot, 0);
  k_basis<<<(MD*NN + 255)/256, 256, 0, st[0]>>>();
  k_fwd0<<<dim3(64, Bq), 256, 0, st[0]>>>(x);
  cudaEventRecord(evD[0], st[0]);
  cudaStreamWaitEvent(st[1], evRoot, 0);
  k_spec_t<<<(NL*WD*WD + 255)/256, 256, 0, st[1]>>>(spec_wr, spec_wi);
  k_prep<<<(NL*WD*WD + 255)/256, 256, 0, st[1]>>>(skip_w, fc1_w);
  cudaEventRecord(evD[1], st[1]);
  cudaStreamWaitEvent(st[2], evRoot, 0);
  k_fc0<<<(Bq*NN*WD/8)/256, 256, 0, st[2]>>>(x, fc0_w, fc0_b);
  cudaEventRecord(evD[2], st[2]);
  cudaStreamWaitEvent(0, evD[0], 0);
  cudaStreamWaitEvent(0, evD[1], 0);
  cudaStreamWaitEvent(0, evD[2], 0);

  for (int l=0; l<NL; l++){
    int last = (l == NL-1);
    k_mix<<<dim3(MD, Bq), 256>>>(l, fc0_w, fc0_b);
    k_layer<<<dim3(NN/128, Bq), 256, 104448>>>(hinH, hinL,
        skip_b + (size_t)l*WD, houtH, houtL, l,
        last ? 0 : 1, last ? 0 : 1,
        last ? 1 : 0, fc1_b, fc2_w, fc2_b, out);
    bf* t;
    t = hinH; hinH = houtH; houtH = t;
    t = hinL; hinL = houtL; houtL = t;
  }
}